// round 3
// baseline (speedup 1.0000x reference)
#include <cuda_runtime.h>

#define N_NODES 50000
#define N_EDGES 800000
#define F_IN    128
#define HIDDEN  256
#define N_GRAPHS 128

// ---------------- scratch (static device globals; no allocation) ----------------
__device__ float g_bufA[N_NODES * HIDDEN];   // GEMM outputs (pre-spmm)
__device__ float g_bufB[N_NODES * HIDDEN];   // spmm outputs (h1 / h2)
__device__ int   g_deg[N_NODES + 1];
__device__ int   g_ptr[N_NODES + 1];
__device__ int   g_fill[N_NODES];
__device__ int   g_csr_src[N_EDGES];
__device__ float g_csr_w[N_EDGES];
__device__ int   g_gstart[N_GRAPHS + 1];
__device__ float g_pool[N_GRAPHS * HIDDEN];

// ---------------- CSR build ----------------
__global__ void k_zero_deg() {
    int i = blockIdx.x * blockDim.x + threadIdx.x;
    if (i <= N_NODES) g_deg[i] = 0;
    if (i < N_NODES)  g_fill[i] = 0;
}

__global__ void k_hist(const int* __restrict__ edge_dst) {
    int e = blockIdx.x * blockDim.x + threadIdx.x;
    if (e < N_EDGES) atomicAdd(&g_deg[edge_dst[e]], 1);
}

// single-block exclusive scan over g_deg -> g_ptr
__global__ void k_scan() {
    __shared__ int tmp[1024];
    __shared__ int carry;
    int tid = threadIdx.x;
    int offset = 0;
    for (int base = 0; base < N_NODES; base += 1024) {
        int i = base + tid;
        int v = (i < N_NODES) ? g_deg[i] : 0;
        tmp[tid] = v;
        __syncthreads();
        for (int d = 1; d < 1024; d <<= 1) {
            int t = (tid >= d) ? tmp[tid - d] : 0;
            __syncthreads();
            tmp[tid] += t;
            __syncthreads();
        }
        if (i < N_NODES) g_ptr[i] = offset + tmp[tid] - v;
        if (tid == 1023) carry = offset + tmp[1023];
        __syncthreads();
        offset = carry;
        __syncthreads();
    }
    if (tid == 0) g_ptr[N_NODES] = offset;
}

__global__ void k_scatter(const int* __restrict__ edge_src,
                          const int* __restrict__ edge_dst,
                          const float* __restrict__ edge_w) {
    int e = blockIdx.x * blockDim.x + threadIdx.x;
    if (e >= N_EDGES) return;
    int d = edge_dst[e];
    int pos = atomicAdd(&g_fill[d], 1);
    int o = g_ptr[d] + pos;
    g_csr_src[o] = edge_src[e];
    g_csr_w[o] = edge_w[e];
}

// ---------------- fp32 SGEMM: C[M,256] = A[M,K] @ B[K,256] ----------------
// 128x128 tile, BK=8, 256 threads, 8x8 microtile (split 4+4 for conflict-free LDS.128)
#define BM 128
#define BN 128
#define BKx 8

__global__ __launch_bounds__(256) void k_sgemm(const float* __restrict__ A,
                                               const float* __restrict__ B,
                                               float* __restrict__ C,
                                               int M, int K, int lda) {
    __shared__ float As[BKx][BM];
    __shared__ float Bs[BKx][BN];
    int tid = threadIdx.x;
    int crow = blockIdx.y * BM;
    int ccol = blockIdx.x * BN;

    int aRow = tid >> 1;            // 0..127
    int aCol = (tid & 1) * 4;       // 0 or 4
    int bRow = tid >> 5;            // 0..7
    int bCol = (tid & 31) * 4;      // 0..124

    int tx = tid & 15;              // 0..15
    int ty = tid >> 4;              // 0..15

    float acc[8][8];
#pragma unroll
    for (int i = 0; i < 8; i++)
#pragma unroll
        for (int j = 0; j < 8; j++) acc[i][j] = 0.0f;

    int nK = K / BKx;
    for (int kt = 0; kt < nK; kt++) {
        int gr = crow + aRow;
        float4 av = make_float4(0.f, 0.f, 0.f, 0.f);
        if (gr < M) av = *(const float4*)&A[(long)gr * lda + kt * BKx + aCol];
        As[aCol + 0][aRow] = av.x;
        As[aCol + 1][aRow] = av.y;
        As[aCol + 2][aRow] = av.z;
        As[aCol + 3][aRow] = av.w;
        *(float4*)&Bs[bRow][bCol] = *(const float4*)&B[(kt * BKx + bRow) * HIDDEN + ccol + bCol];
        __syncthreads();

#pragma unroll
        for (int k = 0; k < BKx; k++) {
            float ra[8], rb[8];
            *(float4*)&ra[0] = *(float4*)&As[k][ty * 4];
            *(float4*)&ra[4] = *(float4*)&As[k][64 + ty * 4];
            *(float4*)&rb[0] = *(float4*)&Bs[k][tx * 4];
            *(float4*)&rb[4] = *(float4*)&Bs[k][64 + tx * 4];
#pragma unroll
            for (int i = 0; i < 8; i++)
#pragma unroll
                for (int j = 0; j < 8; j++)
                    acc[i][j] = fmaf(ra[i], rb[j], acc[i][j]);
        }
        __syncthreads();
    }

#pragma unroll
    for (int ih = 0; ih < 2; ih++) {
#pragma unroll
        for (int i = 0; i < 4; i++) {
            int r = crow + ih * 64 + ty * 4 + i;
            if (r < M) {
                float4 v0 = make_float4(acc[ih * 4 + i][0], acc[ih * 4 + i][1],
                                        acc[ih * 4 + i][2], acc[ih * 4 + i][3]);
                float4 v1 = make_float4(acc[ih * 4 + i][4], acc[ih * 4 + i][5],
                                        acc[ih * 4 + i][6], acc[ih * 4 + i][7]);
                *(float4*)&C[(long)r * HIDDEN + ccol + tx * 4] = v0;
                *(float4*)&C[(long)r * HIDDEN + ccol + 64 + tx * 4] = v1;
            }
        }
    }
}

// ---------------- SpMM via dst-CSR + bias + relu ----------------
// 4 nodes/block, 64 threads/node, each thread a float4 column chunk.
__global__ __launch_bounds__(256) void k_spmm(const float* __restrict__ in,
                                              float* __restrict__ out,
                                              const float* __restrict__ bias) {
    int node = blockIdx.x * 4 + (threadIdx.x >> 6);
    if (node >= N_NODES) return;
    int lane = threadIdx.x & 63;
    int c = lane * 4;
    int beg = g_ptr[node], end = g_ptr[node + 1];

    float4 acc = make_float4(0.f, 0.f, 0.f, 0.f);
    int e = beg;
    for (; e + 4 <= end; e += 4) {
        int s0 = g_csr_src[e], s1 = g_csr_src[e + 1];
        int s2 = g_csr_src[e + 2], s3 = g_csr_src[e + 3];
        float w0 = g_csr_w[e], w1 = g_csr_w[e + 1];
        float w2 = g_csr_w[e + 2], w3 = g_csr_w[e + 3];
        float4 v0 = *(const float4*)&in[(long)s0 * HIDDEN + c];
        float4 v1 = *(const float4*)&in[(long)s1 * HIDDEN + c];
        float4 v2 = *(const float4*)&in[(long)s2 * HIDDEN + c];
        float4 v3 = *(const float4*)&in[(long)s3 * HIDDEN + c];
        acc.x = fmaf(v0.x, w0, acc.x); acc.y = fmaf(v0.y, w0, acc.y);
        acc.z = fmaf(v0.z, w0, acc.z); acc.w = fmaf(v0.w, w0, acc.w);
        acc.x = fmaf(v1.x, w1, acc.x); acc.y = fmaf(v1.y, w1, acc.y);
        acc.z = fmaf(v1.z, w1, acc.z); acc.w = fmaf(v1.w, w1, acc.w);
        acc.x = fmaf(v2.x, w2, acc.x); acc.y = fmaf(v2.y, w2, acc.y);
        acc.z = fmaf(v2.z, w2, acc.z); acc.w = fmaf(v2.w, w2, acc.w);
        acc.x = fmaf(v3.x, w3, acc.x); acc.y = fmaf(v3.y, w3, acc.y);
        acc.z = fmaf(v3.z, w3, acc.z); acc.w = fmaf(v3.w, w3, acc.w);
    }
    for (; e < end; e++) {
        int s = g_csr_src[e];
        float w = g_csr_w[e];
        float4 v = *(const float4*)&in[(long)s * HIDDEN + c];
        acc.x = fmaf(v.x, w, acc.x); acc.y = fmaf(v.y, w, acc.y);
        acc.z = fmaf(v.z, w, acc.z); acc.w = fmaf(v.w, w, acc.w);
    }
    float4 b = *(const float4*)&bias[c];
    acc.x = fmaxf(acc.x + b.x, 0.f);
    acc.y = fmaxf(acc.y + b.y, 0.f);
    acc.z = fmaxf(acc.z + b.z, 0.f);
    acc.w = fmaxf(acc.w + b.w, 0.f);
    *(float4*)&out[(long)node * HIDDEN + c] = acc;
}

// ---------------- segment starts (seg_ids is sorted) ----------------
__global__ void k_gstart(const int* __restrict__ seg_ids) {
    int i = blockIdx.x * blockDim.x + threadIdx.x;
    if (i >= N_NODES) return;
    int s = seg_ids[i];
    int p = (i > 0) ? seg_ids[i - 1] : -1;
    for (int g = p + 1; g <= s; g++) g_gstart[g] = i;
    if (i == N_NODES - 1)
        for (int g = s + 1; g <= N_GRAPHS; g++) g_gstart[g] = N_NODES;
}

// ---------------- pooling: g_pool[g][f] = sum of h rows in segment g ----------------
__global__ __launch_bounds__(256) void k_pool(const float* __restrict__ h) {
    int g = blockIdx.x;
    int f = threadIdx.x;
    int beg = g_gstart[g], end = g_gstart[g + 1];
    float acc0 = 0.f, acc1 = 0.f, acc2 = 0.f, acc3 = 0.f;
    int n = beg;
    for (; n + 4 <= end; n += 4) {
        acc0 += h[(long)n * HIDDEN + f];
        acc1 += h[(long)(n + 1) * HIDDEN + f];
        acc2 += h[(long)(n + 2) * HIDDEN + f];
        acc3 += h[(long)(n + 3) * HIDDEN + f];
    }
    for (; n < end; n++) acc0 += h[(long)n * HIDDEN + f];
    g_pool[g * HIDDEN + f] = (acc0 + acc1) + (acc2 + acc3);
}

// ---------------- dense head: out[g] = relu(pool@Wd+bd) @ Wo + bo ----------------
__global__ __launch_bounds__(256) void k_head(const float* __restrict__ Wd,
                                              const float* __restrict__ bd,
                                              const float* __restrict__ Wo,
                                              const float* __restrict__ bo,
                                              float* __restrict__ out) {
    __shared__ float pg[HIDDEN];
    __shared__ float red[256];
    int g = blockIdx.x;
    int j = threadIdx.x;
    pg[j] = g_pool[g * HIDDEN + j];
    __syncthreads();
    float acc = 0.f;
#pragma unroll 8
    for (int k = 0; k < HIDDEN; k++)
        acc = fmaf(pg[k], Wd[k * HIDDEN + j], acc);
    float v = fmaxf(acc + bd[j], 0.f);
    red[j] = v * Wo[j];
    __syncthreads();
    for (int s = 128; s > 0; s >>= 1) {
        if (j < s) red[j] += red[j + s];
        __syncthreads();
    }
    if (j == 0) out[g] = red[0] + bo[0];
}

// ---------------- launch ----------------
extern "C" void kernel_launch(void* const* d_in, const int* in_sizes, int n_in,
                              void* d_out, int out_size) {
    const float* x        = (const float*)d_in[0];
    const int*   edge_src = (const int*)d_in[1];
    const int*   edge_dst = (const int*)d_in[2];
    const float* edge_w   = (const float*)d_in[3];
    const int*   seg_ids  = (const int*)d_in[4];
    const float* W1       = (const float*)d_in[5];
    const float* b1       = (const float*)d_in[6];
    const float* W2       = (const float*)d_in[7];
    const float* b2       = (const float*)d_in[8];
    const float* Wd       = (const float*)d_in[9];
    const float* bd       = (const float*)d_in[10];
    const float* Wo       = (const float*)d_in[11];
    const float* bo       = (const float*)d_in[12];
    float* out = (float*)d_out;

    float* bufA; cudaGetSymbolAddress((void**)&bufA, g_bufA);
    float* bufB; cudaGetSymbolAddress((void**)&bufB, g_bufB);

    // CSR build (per call; deterministic up to fp sum order)
    k_zero_deg<<<(N_NODES + 256) / 256, 256>>>();
    k_hist<<<(N_EDGES + 255) / 256, 256>>>(edge_dst);
    k_scan<<<1, 1024>>>();
    k_scatter<<<(N_EDGES + 255) / 256, 256>>>(edge_src, edge_dst, edge_w);
    k_gstart<<<(N_NODES + 255) / 256, 256>>>(seg_ids);

    dim3 gemmGrid(HIDDEN / BN, (N_NODES + BM - 1) / BM);

    // layer 1: bufA = x @ W1 ; bufB = relu(spmm(bufA) + b1)
    k_sgemm<<<gemmGrid, 256>>>(x, W1, bufA, N_NODES, F_IN, F_IN);
    k_spmm<<<(N_NODES + 3) / 4, 256>>>(bufA, bufB, b1);

    // layer 2: bufA = bufB @ W2 ; bufB = relu(spmm(bufA) + b2)
    k_sgemm<<<gemmGrid, 256>>>(bufB, W2, bufA, N_NODES, HIDDEN, HIDDEN);
    k_spmm<<<(N_NODES + 3) / 4, 256>>>(bufA, bufB, b2);

    // pool + head
    k_pool<<<N_GRAPHS, HIDDEN>>>(bufB);
    k_head<<<N_GRAPHS, HIDDEN>>>(Wd, bd, Wo, bo, out);
}

// round 5
// speedup vs baseline: 1.9258x; 1.9258x over previous
#include <cuda_runtime.h>
#include <cstdint>

#define N_NODES 50000
#define N_EDGES 800000
#define F_IN    128
#define HIDDEN  256
#define N_GRAPHS 128

#define SCAN_B  512
#define SCAN_NB ((N_NODES + SCAN_B - 1) / SCAN_B)

// ---------------- scratch (static device globals; no allocation) ----------------
__device__ float g_bufA[N_NODES * HIDDEN];
__device__ float g_bufB[N_NODES * HIDDEN];
__device__ int   g_deg[N_NODES + 1];
__device__ int   g_ptr[N_NODES + 1];
__device__ int   g_fill[N_NODES];
__device__ int   g_csr_src[N_EDGES];
__device__ float g_csr_w[N_EDGES];
__device__ int   g_gstart[N_GRAPHS + 1];
__device__ float g_pool[N_GRAPHS * HIDDEN];
__device__ int   g_bsum2[SCAN_NB];

// ---------------- CSR build ----------------
__global__ void k_zero_deg() {
    int i = blockIdx.x * blockDim.x + threadIdx.x;
    if (i <= N_NODES) g_deg[i] = 0;
    if (i < N_NODES)  g_fill[i] = 0;
}

__global__ void k_hist(const int* __restrict__ edge_dst) {
    int e = blockIdx.x * blockDim.x + threadIdx.x;
    if (e < N_EDGES) atomicAdd(&g_deg[edge_dst[e]], 1);
}

// block-local exclusive scan; block sums to g_bsum2
__global__ __launch_bounds__(SCAN_B) void k_scan_block() {
    __shared__ int wsum[SCAN_B / 32];
    int t = threadIdx.x;
    int lane = t & 31, wid = t >> 5;
    int i = blockIdx.x * SCAN_B + t;
    int v = (i < N_NODES) ? g_deg[i] : 0;
    int incl = v;
#pragma unroll
    for (int o = 1; o < 32; o <<= 1) {
        int n = __shfl_up_sync(0xffffffffu, incl, o);
        if (lane >= o) incl += n;
    }
    if (lane == 31) wsum[wid] = incl;
    __syncthreads();
    if (t < SCAN_B / 32) {
        int s = wsum[t];
        int inc = s;
#pragma unroll
        for (int o = 1; o < SCAN_B / 32; o <<= 1) {
            int n = __shfl_up_sync(0xffffu, inc, o);
            if (t >= o) inc += n;
        }
        wsum[t] = inc - s;  // exclusive warp prefix
        if (t == SCAN_B / 32 - 1) g_bsum2[blockIdx.x] = inc;
    }
    __syncthreads();
    if (i < N_NODES) g_ptr[i] = wsum[wid] + incl - v;
}

// scan the block partials (SCAN_NB <= 128)
__global__ void k_scan_tops() {
    __shared__ int ws[4];
    int t = threadIdx.x, lane = t & 31, wid = t >> 5;
    int v = (t < SCAN_NB) ? g_bsum2[t] : 0;
    int incl = v;
#pragma unroll
    for (int o = 1; o < 32; o <<= 1) {
        int n = __shfl_up_sync(0xffffffffu, incl, o);
        if (lane >= o) incl += n;
    }
    if (lane == 31) ws[wid] = incl;
    __syncthreads();
    if (t == 0) {
        int s = 0;
#pragma unroll
        for (int i = 0; i < 4; i++) { int x = ws[i]; ws[i] = s; s += x; }
        g_ptr[N_NODES] = s;
    }
    __syncthreads();
    if (t < SCAN_NB) g_bsum2[t] = ws[wid] + incl - v;
}

__global__ __launch_bounds__(SCAN_B) void k_add_off() {
    int i = blockIdx.x * SCAN_B + threadIdx.x;
    if (i < N_NODES) g_ptr[i] += g_bsum2[blockIdx.x];
}

__global__ void k_scatter(const int* __restrict__ edge_src,
                          const int* __restrict__ edge_dst,
                          const float* __restrict__ edge_w) {
    int e = blockIdx.x * blockDim.x + threadIdx.x;
    if (e >= N_EDGES) return;
    int d = edge_dst[e];
    int pos = atomicAdd(&g_fill[d], 1);
    int o = g_ptr[d] + pos;
    g_csr_src[o] = edge_src[e];
    g_csr_w[o] = edge_w[e];
}

__global__ void k_gstart(const int* __restrict__ seg_ids) {
    int i = blockIdx.x * blockDim.x + threadIdx.x;
    if (i >= N_NODES) return;
    int s = seg_ids[i];
    int p = (i > 0) ? seg_ids[i - 1] : -1;
    for (int g = p + 1; g <= s; g++) g_gstart[g] = i;
    if (i == N_NODES - 1)
        for (int g = s + 1; g <= N_GRAPHS; g++) g_gstart[g] = N_NODES;
}

// ---------------- tf32 tensor GEMM: C = relu(A[M,K] @ B[K,256] + bias) ----------------
// 128x128 block tile, BK=32, 256 threads (8 warps in 2(M)x4(N)), warp tile 64x32.
// mma.sync.m16n8k8 tf32, fp32 accumulate.
#define GBM 128
#define GBN 128
#define GBK 32
#define AS_STRIDE 36    // 32 + 4 pad (floats)
#define BS_STRIDE 132   // 128 + 4 pad (floats)

__device__ __forceinline__ float f2tf32(float x) {
    uint32_t o;
    asm("cvt.rna.tf32.f32 %0, %1;" : "=r"(o) : "f"(x));
    return __uint_as_float(o);
}

__global__ __launch_bounds__(256) void k_gemm_tf32(const float* __restrict__ A,
                                                   int K,
                                                   const float* __restrict__ Bw,
                                                   const float* __restrict__ bias,
                                                   float* __restrict__ C,
                                                   int M) {
    __shared__ float As[GBM * AS_STRIDE];   // [row][k], tf32 bit patterns
    __shared__ float Bs[GBK * BS_STRIDE];   // [k][n],  tf32 bit patterns

    int tid  = threadIdx.x;
    int lane = tid & 31;
    int warp = tid >> 5;
    int wm = warp & 1;        // 0..1  -> M offset 0/64
    int wn = warp >> 1;       // 0..3  -> N offset 0/32/64/96

    int rowBase = blockIdx.y * GBM;
    int colBase = blockIdx.x * GBN;

    float acc[4][4][4];
#pragma unroll
    for (int mi = 0; mi < 4; mi++)
#pragma unroll
        for (int ni = 0; ni < 4; ni++)
#pragma unroll
            for (int r = 0; r < 4; r++) acc[mi][ni][r] = 0.0f;

    for (int kt = 0; kt < K; kt += GBK) {
        // load A tile: 128x32 floats, 4 float4 per thread
#pragma unroll
        for (int i = 0; i < 4; i++) {
            int f = tid + 256 * i;
            int row = f >> 3;             // 0..127
            int kc  = (f & 7) * 4;        // 0..28
            int gr = rowBase + row;
            float4 v = make_float4(0.f, 0.f, 0.f, 0.f);
            if (gr < M) v = *(const float4*)&A[(long)gr * K + kt + kc];
            float4 t4 = make_float4(f2tf32(v.x), f2tf32(v.y), f2tf32(v.z), f2tf32(v.w));
            *(float4*)&As[row * AS_STRIDE + kc] = t4;
        }
        // load B tile: 32x128 floats, 4 float4 per thread
#pragma unroll
        for (int i = 0; i < 4; i++) {
            int f = tid + 256 * i;
            int krow = f >> 5;            // 0..31
            int nc   = (f & 31) * 4;      // 0..124
            float4 v = *(const float4*)&Bw[(long)(kt + krow) * HIDDEN + colBase + nc];
            float4 t4 = make_float4(f2tf32(v.x), f2tf32(v.y), f2tf32(v.z), f2tf32(v.w));
            *(float4*)&Bs[krow * BS_STRIDE + nc] = t4;
        }
        __syncthreads();

#pragma unroll
        for (int kk = 0; kk < GBK; kk += 8) {
            uint32_t afr[4][4], bfr[4][2];
#pragma unroll
            for (int mi = 0; mi < 4; mi++) {
                int r0 = wm * 64 + mi * 16 + (lane >> 2);
                int kc = kk + (lane & 3);
                afr[mi][0] = __float_as_uint(As[r0 * AS_STRIDE + kc]);
                afr[mi][1] = __float_as_uint(As[(r0 + 8) * AS_STRIDE + kc]);
                afr[mi][2] = __float_as_uint(As[r0 * AS_STRIDE + kc + 4]);
                afr[mi][3] = __float_as_uint(As[(r0 + 8) * AS_STRIDE + kc + 4]);
            }
#pragma unroll
            for (int ni = 0; ni < 4; ni++) {
                int cb = wn * 32 + ni * 8 + (lane >> 2);
                int kc = kk + (lane & 3);
                bfr[ni][0] = __float_as_uint(Bs[kc * BS_STRIDE + cb]);
                bfr[ni][1] = __float_as_uint(Bs[(kc + 4) * BS_STRIDE + cb]);
            }
#pragma unroll
            for (int mi = 0; mi < 4; mi++)
#pragma unroll
                for (int ni = 0; ni < 4; ni++) {
                    asm volatile(
                        "mma.sync.aligned.m16n8k8.row.col.f32.tf32.tf32.f32 "
                        "{%0,%1,%2,%3}, {%4,%5,%6,%7}, {%8,%9}, {%0,%1,%2,%3};"
                        : "+f"(acc[mi][ni][0]), "+f"(acc[mi][ni][1]),
                          "+f"(acc[mi][ni][2]), "+f"(acc[mi][ni][3])
                        : "r"(afr[mi][0]), "r"(afr[mi][1]),
                          "r"(afr[mi][2]), "r"(afr[mi][3]),
                          "r"(bfr[ni][0]), "r"(bfr[ni][1]));
                }
        }
        __syncthreads();
    }

    // epilogue: bias + relu + store
#pragma unroll
    for (int mi = 0; mi < 4; mi++) {
        int r0 = rowBase + wm * 64 + mi * 16 + (lane >> 2);
#pragma unroll
        for (int ni = 0; ni < 4; ni++) {
            int col = colBase + wn * 32 + ni * 8 + (lane & 3) * 2;
            float b0 = bias[col], b1v = bias[col + 1];
            if (r0 < M) {
                float2 o;
                o.x = fmaxf(acc[mi][ni][0] + b0, 0.f);
                o.y = fmaxf(acc[mi][ni][1] + b1v, 0.f);
                *(float2*)&C[(long)r0 * HIDDEN + col] = o;
            }
            if (r0 + 8 < M) {
                float2 o;
                o.x = fmaxf(acc[mi][ni][2] + b0, 0.f);
                o.y = fmaxf(acc[mi][ni][3] + b1v, 0.f);
                *(float2*)&C[(long)(r0 + 8) * HIDDEN + col] = o;
            }
        }
    }
}

// ---------------- SpMM (pure gather-sum, no bias/relu) ----------------
// 128-col version: 1 warp per node, float4 per lane.
__global__ __launch_bounds__(256) void k_spmm128(const float* __restrict__ in,
                                                 float* __restrict__ out) {
    int node = blockIdx.x * 8 + (threadIdx.x >> 5);
    if (node >= N_NODES) return;
    int c = (threadIdx.x & 31) * 4;
    int beg = g_ptr[node], end = g_ptr[node + 1];

    float4 acc = make_float4(0.f, 0.f, 0.f, 0.f);
    int e = beg;
    for (; e + 4 <= end; e += 4) {
        int s0 = g_csr_src[e], s1 = g_csr_src[e + 1];
        int s2 = g_csr_src[e + 2], s3 = g_csr_src[e + 3];
        float w0 = g_csr_w[e], w1 = g_csr_w[e + 1];
        float w2 = g_csr_w[e + 2], w3 = g_csr_w[e + 3];
        float4 v0 = *(const float4*)&in[(long)s0 * F_IN + c];
        float4 v1 = *(const float4*)&in[(long)s1 * F_IN + c];
        float4 v2 = *(const float4*)&in[(long)s2 * F_IN + c];
        float4 v3 = *(const float4*)&in[(long)s3 * F_IN + c];
        acc.x = fmaf(v0.x, w0, acc.x); acc.y = fmaf(v0.y, w0, acc.y);
        acc.z = fmaf(v0.z, w0, acc.z); acc.w = fmaf(v0.w, w0, acc.w);
        acc.x = fmaf(v1.x, w1, acc.x); acc.y = fmaf(v1.y, w1, acc.y);
        acc.z = fmaf(v1.z, w1, acc.z); acc.w = fmaf(v1.w, w1, acc.w);
        acc.x = fmaf(v2.x, w2, acc.x); acc.y = fmaf(v2.y, w2, acc.y);
        acc.z = fmaf(v2.z, w2, acc.z); acc.w = fmaf(v2.w, w2, acc.w);
        acc.x = fmaf(v3.x, w3, acc.x); acc.y = fmaf(v3.y, w3, acc.y);
        acc.z = fmaf(v3.z, w3, acc.z); acc.w = fmaf(v3.w, w3, acc.w);
    }
    for (; e < end; e++) {
        int s = g_csr_src[e];
        float w = g_csr_w[e];
        float4 v = *(const float4*)&in[(long)s * F_IN + c];
        acc.x = fmaf(v.x, w, acc.x); acc.y = fmaf(v.y, w, acc.y);
        acc.z = fmaf(v.z, w, acc.z); acc.w = fmaf(v.w, w, acc.w);
    }
    *(float4*)&out[(long)node * F_IN + c] = acc;
}

// 256-col version: 64 threads per node.
__global__ __launch_bounds__(256) void k_spmm256(const float* __restrict__ in,
                                                 float* __restrict__ out) {
    int node = blockIdx.x * 4 + (threadIdx.x >> 6);
    if (node >= N_NODES) return;
    int c = (threadIdx.x & 63) * 4;
    int beg = g_ptr[node], end = g_ptr[node + 1];

    float4 acc = make_float4(0.f, 0.f, 0.f, 0.f);
    int e = beg;
    for (; e + 4 <= end; e += 4) {
        int s0 = g_csr_src[e], s1 = g_csr_src[e + 1];
        int s2 = g_csr_src[e + 2], s3 = g_csr_src[e + 3];
        float w0 = g_csr_w[e], w1 = g_csr_w[e + 1];
        float w2 = g_csr_w[e + 2], w3 = g_csr_w[e + 3];
        float4 v0 = *(const float4*)&in[(long)s0 * HIDDEN + c];
        float4 v1 = *(const float4*)&in[(long)s1 * HIDDEN + c];
        float4 v2 = *(const float4*)&in[(long)s2 * HIDDEN + c];
        float4 v3 = *(const float4*)&in[(long)s3 * HIDDEN + c];
        acc.x = fmaf(v0.x, w0, acc.x); acc.y = fmaf(v0.y, w0, acc.y);
        acc.z = fmaf(v0.z, w0, acc.z); acc.w = fmaf(v0.w, w0, acc.w);
        acc.x = fmaf(v1.x, w1, acc.x); acc.y = fmaf(v1.y, w1, acc.y);
        acc.z = fmaf(v1.z, w1, acc.z); acc.w = fmaf(v1.w, w1, acc.w);
        acc.x = fmaf(v2.x, w2, acc.x); acc.y = fmaf(v2.y, w2, acc.y);
        acc.z = fmaf(v2.z, w2, acc.z); acc.w = fmaf(v2.w, w2, acc.w);
        acc.x = fmaf(v3.x, w3, acc.x); acc.y = fmaf(v3.y, w3, acc.y);
        acc.z = fmaf(v3.z, w3, acc.z); acc.w = fmaf(v3.w, w3, acc.w);
    }
    for (; e < end; e++) {
        int s = g_csr_src[e];
        float w = g_csr_w[e];
        float4 v = *(const float4*)&in[(long)s * HIDDEN + c];
        acc.x = fmaf(v.x, w, acc.x); acc.y = fmaf(v.y, w, acc.y);
        acc.z = fmaf(v.z, w, acc.z); acc.w = fmaf(v.w, w, acc.w);
    }
    *(float4*)&out[(long)node * HIDDEN + c] = acc;
}

// ---------------- pooling ----------------
__global__ __launch_bounds__(256) void k_pool(const float* __restrict__ h) {
    int g = blockIdx.x;
    int f = threadIdx.x;
    int beg = g_gstart[g], end = g_gstart[g + 1];
    float acc0 = 0.f, acc1 = 0.f, acc2 = 0.f, acc3 = 0.f;
    int n = beg;
    for (; n + 4 <= end; n += 4) {
        acc0 += h[(long)n * HIDDEN + f];
        acc1 += h[(long)(n + 1) * HIDDEN + f];
        acc2 += h[(long)(n + 2) * HIDDEN + f];
        acc3 += h[(long)(n + 3) * HIDDEN + f];
    }
    for (; n < end; n++) acc0 += h[(long)n * HIDDEN + f];
    g_pool[g * HIDDEN + f] = (acc0 + acc1) + (acc2 + acc3);
}

// ---------------- dense head ----------------
__global__ __launch_bounds__(256) void k_head(const float* __restrict__ Wd,
                                              const float* __restrict__ bd,
                                              const float* __restrict__ Wo,
                                              const float* __restrict__ bo,
                                              float* __restrict__ out) {
    __shared__ float pg[HIDDEN];
    __shared__ float red[256];
    int g = blockIdx.x;
    int j = threadIdx.x;
    pg[j] = g_pool[g * HIDDEN + j];
    __syncthreads();
    float acc = 0.f;
#pragma unroll 8
    for (int k = 0; k < HIDDEN; k++)
        acc = fmaf(pg[k], Wd[k * HIDDEN + j], acc);
    float v = fmaxf(acc + bd[j], 0.f);
    red[j] = v * Wo[j];
    __syncthreads();
    for (int s = 128; s > 0; s >>= 1) {
        if (j < s) red[j] += red[j + s];
        __syncthreads();
    }
    if (j == 0) out[g] = red[0] + bo[0];
}

// ---------------- launch ----------------
extern "C" void kernel_launch(void* const* d_in, const int* in_sizes, int n_in,
                              void* d_out, int out_size) {
    const float* x        = (const float*)d_in[0];
    const int*   edge_src = (const int*)d_in[1];
    const int*   edge_dst = (const int*)d_in[2];
    const float* edge_w   = (const float*)d_in[3];
    const int*   seg_ids  = (const int*)d_in[4];
    const float* W1       = (const float*)d_in[5];
    const float* b1       = (const float*)d_in[6];
    const float* W2       = (const float*)d_in[7];
    const float* b2       = (const float*)d_in[8];
    const float* Wd       = (const float*)d_in[9];
    const float* bd       = (const float*)d_in[10];
    const float* Wo       = (const float*)d_in[11];
    const float* bo       = (const float*)d_in[12];
    float* out = (float*)d_out;

    float* bufA; cudaGetSymbolAddress((void**)&bufA, g_bufA);
    float* bufB; cudaGetSymbolAddress((void**)&bufB, g_bufB);

    // CSR build
    k_zero_deg<<<(N_NODES + 256) / 256, 256>>>();
    k_hist<<<(N_EDGES + 255) / 256, 256>>>(edge_dst);
    k_scan_block<<<SCAN_NB, SCAN_B>>>();
    k_scan_tops<<<1, 128>>>();
    k_add_off<<<SCAN_NB, SCAN_B>>>();
    k_scatter<<<(N_EDGES + 255) / 256, 256>>>(edge_src, edge_dst, edge_w);
    k_gstart<<<(N_NODES + 255) / 256, 256>>>(seg_ids);

    dim3 gemmGrid(HIDDEN / GBN, (N_NODES + GBM - 1) / GBM);

    // layer 1 (reordered): s1 = A@x (128 cols); h1 = relu(s1 @ W1 + b1)
    k_spmm128<<<(N_NODES + 7) / 8, 256>>>(x, bufA);
    k_gemm_tf32<<<gemmGrid, 256>>>(bufA, F_IN, W1, b1, bufB, N_NODES);

    // layer 2 (reordered): s2 = A@h1 (256 cols); h2 = relu(s2 @ W2 + b2)
    k_spmm256<<<(N_NODES + 3) / 4, 256>>>(bufB, bufA);
    k_gemm_tf32<<<gemmGrid, 256>>>(bufA, HIDDEN, W2, b2, bufB, N_NODES);

    // pool + head
    k_pool<<<N_GRAPHS, HIDDEN>>>(bufB);
    k_head<<<N_GRAPHS, HIDDEN>>>(Wd, bd, Wo, bo, out);
}